// round 1
// baseline (speedup 1.0000x reference)
#include <cuda_runtime.h>

#define Bq 2
#define Cc 16
#define Hh 128
#define Ww 128
#define HWp (Hh*Ww)

// ---------------- static device scratch (no allocations) ----------------
__device__ float g_att_bg[3][(size_t)Bq*64*HWp];          // 24 MB
__device__ float g_att_tg[3][(size_t)Bq*8*HWp];           // 3 MB
__device__ float g_feats[2][3][(size_t)Bq*Cc*HWp];        // 12 MB
__device__ float g_pooled[2][Bq*Cc];
__device__ float g_wt[2][Bq*3*Cc];
// transposed memory copies:
//   A-layout: [c][d][m]   (m contiguous)  -> for logits kernel
//   B-layout: [m][d][c]   (c contiguous)  -> for fold kernel
__device__ float g_memA_bg[3][64*Cc*49];
__device__ float g_memA_tg[3][8*Cc*49];
__device__ float g_memB_bg[3][64*Cc*49];
__device__ float g_memB_tg[3][8*Cc*49];

// ---------------- mem transpose ----------------
template<int P, int M>
__global__ void transpose_mem_kernel(const float* __restrict__ mem, int s) {
    float* A  = (M==64) ? g_memA_bg[s] : g_memA_tg[s];
    float* Bm = (M==64) ? g_memB_bg[s] : g_memB_tg[s];
    const int PP = P*P;
    const int n = M*Cc*PP;
    for (int idx = blockIdx.x*blockDim.x + threadIdx.x; idx < n; idx += gridDim.x*blockDim.x) {
        int m   = idx / (Cc*PP);
        int rem = idx % (Cc*PP);
        int c   = rem / PP;
        int d   = rem % PP;
        float v = mem[idx];
        A[(c*PP + d)*M + m]  = v;
        Bm[(m*PP + d)*Cc + c] = v;
    }
}

// ---------------- logits + softmax (implicit-GEMM sim) ----------------
// block = 16x8 pixels, thread-per-pixel, M accumulators in registers.
template<int P, int M>
__global__ void logits_kernel(const float* __restrict__ x,
                              const float* __restrict__ temp, int s) {
    constexpr int PAD = P/2;
    constexpr int TX = 16, TY = 8;
    constexpr int SW = TX + P - 1, SH = TY + P - 1;
    constexpr int PP = P*P;
    __shared__ __align__(16) float xs[Cc][SH][SW];
    __shared__ __align__(16) float ms[PP*M];     // [d][m], m contiguous

    const float* memA = (M==64) ? g_memA_bg[s] : g_memA_tg[s];
    float* att        = (M==64) ? g_att_bg[s]  : g_att_tg[s];

    const int b  = blockIdx.z;
    const int x0 = blockIdx.x * TX, y0 = blockIdx.y * TY;
    const int tx = threadIdx.x, ty = threadIdx.y;
    const int tid = ty*TX + tx;
    const int NT  = TX*TY;

    // load x tile with halo (zero-padded)
    for (int idx = tid; idx < Cc*SH*SW; idx += NT) {
        int c = idx / (SH*SW);
        int r = idx % (SH*SW);
        int ry = r / SW, rx = r % SW;
        int gy = y0 + ry - PAD, gx = x0 + rx - PAD;
        float v = 0.f;
        if (gy >= 0 && gy < Hh && gx >= 0 && gx < Ww)
            v = x[((size_t)(b*Cc + c)*Hh + gy)*Ww + gx];
        xs[c][ry][rx] = v;
    }

    float acc[M];
    #pragma unroll
    for (int m = 0; m < M; m++) acc[m] = 0.f;

    for (int c = 0; c < Cc; c++) {
        __syncthreads();
        for (int idx = tid; idx < PP*M; idx += NT)
            ms[idx] = memA[(size_t)c*PP*M + idx];
        __syncthreads();
        for (int i = 0; i < P; i++) {
            for (int j = 0; j < P; j++) {
                float xv = xs[c][ty + i][tx + j];
                const float4* mp = reinterpret_cast<const float4*>(&ms[(i*P + j)*M]);
                #pragma unroll
                for (int m4 = 0; m4 < M/4; m4++) {
                    float4 w = mp[m4];
                    acc[4*m4+0] = fmaf(xv, w.x, acc[4*m4+0]);
                    acc[4*m4+1] = fmaf(xv, w.y, acc[4*m4+1]);
                    acc[4*m4+2] = fmaf(xv, w.z, acc[4*m4+2]);
                    acc[4*m4+3] = fmaf(xv, w.w, acc[4*m4+3]);
                }
            }
        }
    }

    // softmax over M (scale = temp / sqrt(D))
    float scale = temp[0] / sqrtf((float)(Cc*PP));
    float mx = acc[0];
    #pragma unroll
    for (int m = 1; m < M; m++) mx = fmaxf(mx, acc[m]);
    float ssum = 0.f;
    #pragma unroll
    for (int m = 0; m < M; m++) { acc[m] = __expf(scale*(acc[m]-mx)); ssum += acc[m]; }
    float inv = 1.f / ssum;

    int gy = y0 + ty, gx = x0 + tx;
    #pragma unroll
    for (int m = 0; m < M; m++)
        att[((size_t)(b*M + m)*Hh + gy)*Ww + gx] = acc[m]*inv;
}

// ---------------- readout + fold (transposed-conv over att maps) ----------------
template<int P, int M, int MC>
__global__ void fold_kernel(int s) {
    constexpr int PAD = P/2;
    constexpr int TX = 16, TY = 8;
    constexpr int SW = TX + P - 1, SH = TY + P - 1;
    constexpr int PP = P*P;
    __shared__ __align__(16) float as_[MC][SH][SW];
    __shared__ __align__(16) float msB[MC*PP*Cc];   // [m][d][c], c contiguous

    const float* att  = (M==64) ? g_att_bg[s]  : g_att_tg[s];
    const float* memB = (M==64) ? g_memB_bg[s] : g_memB_tg[s];
    float* feat       = g_feats[(M==64)?0:1][s];

    const int b  = blockIdx.z;
    const int x0 = blockIdx.x*TX, y0 = blockIdx.y*TY;
    const int tx = threadIdx.x, ty = threadIdx.y;
    const int tid = ty*TX+tx;
    const int NT  = TX*TY;

    float acc[Cc];
    #pragma unroll
    for (int c = 0; c < Cc; c++) acc[c] = 0.f;

    for (int m0 = 0; m0 < M; m0 += MC) {
        __syncthreads();
        for (int idx = tid; idx < MC*SH*SW; idx += NT) {
            int ml = idx/(SH*SW); int r = idx%(SH*SW);
            int ry = r/SW, rx = r%SW;
            int gy = y0+ry-PAD, gx = x0+rx-PAD;
            float v = 0.f;
            if (gy >= 0 && gy < Hh && gx >= 0 && gx < Ww)
                v = att[((size_t)(b*M + m0+ml)*Hh + gy)*Ww + gx];
            as_[ml][ry][rx] = v;
        }
        for (int idx = tid; idx < MC*PP*Cc; idx += NT)
            msB[idx] = memB[(size_t)m0*PP*Cc + idx];
        __syncthreads();
        for (int ml = 0; ml < MC; ml++) {
            for (int i = 0; i < P; i++) {
                for (int j = 0; j < P; j++) {
                    float av = as_[ml][ty + (P-1-i)][tx + (P-1-j)];
                    const float4* mp = reinterpret_cast<const float4*>(&msB[(ml*PP + i*P + j)*Cc]);
                    #pragma unroll
                    for (int c4 = 0; c4 < Cc/4; c4++) {
                        float4 w = mp[c4];
                        acc[4*c4+0] = fmaf(av, w.x, acc[4*c4+0]);
                        acc[4*c4+1] = fmaf(av, w.y, acc[4*c4+1]);
                        acc[4*c4+2] = fmaf(av, w.z, acc[4*c4+2]);
                        acc[4*c4+3] = fmaf(av, w.w, acc[4*c4+3]);
                    }
                }
            }
        }
    }

    int gy = y0+ty, gx = x0+tx;
    int cy = min(gy,PAD) + min(Hh-1-gy,PAD) + 1;   // analytic fold-of-ones divisor
    int cx = min(gx,PAD) + min(Ww-1-gx,PAD) + 1;
    float invd = 1.f/((float)(cy*cx) + 1e-8f);
    #pragma unroll
    for (int c = 0; c < Cc; c++)
        feat[((size_t)(b*Cc+c)*Hh+gy)*Ww+gx] = acc[c]*invd;
}

// ---------------- fusion ----------------
__global__ void pool_kernel() {
    int bi = blockIdx.x;                // 0..63
    int branch = bi >> 5;               // Bq*Cc = 32
    int r = bi & 31;
    const float* f0 = g_feats[branch][0] + (size_t)r*HWp;
    const float* f1 = g_feats[branch][1] + (size_t)r*HWp;
    const float* f2 = g_feats[branch][2] + (size_t)r*HWp;
    float sv = 0.f;
    for (int i = threadIdx.x; i < HWp; i += blockDim.x)
        sv += f0[i] + f1[i] + f2[i];
    __shared__ float red[256];
    red[threadIdx.x] = sv;
    __syncthreads();
    for (int off = 128; off > 0; off >>= 1) {
        if (threadIdx.x < off) red[threadIdx.x] += red[threadIdx.x + off];
        __syncthreads();
    }
    if (threadIdx.x == 0) g_pooled[branch][r] = red[0] / (float)HWp;
}

__global__ void fuse_wt_kernel(const float* __restrict__ bw1, const float* __restrict__ bb1,
                               const float* __restrict__ bw2, const float* __restrict__ bb2,
                               const float* __restrict__ tw1, const float* __restrict__ tb1,
                               const float* __restrict__ tw2, const float* __restrict__ tb2) {
    int t = threadIdx.x;
    if (t >= 2*Bq*Cc) return;
    int branch = t / (Bq*Cc);
    int r = t % (Bq*Cc);
    int b = r / Cc, c = r % Cc;
    const float* w1 = branch ? tw1 : bw1;
    const float* b1 = branch ? tb1 : bb1;
    const float* w2 = branch ? tw2 : bw2;
    const float* b2 = branch ? tb2 : bb2;
    float hdn[4];
    for (int h = 0; h < 4; h++) {
        float sv = b1[h];
        for (int cc = 0; cc < Cc; cc++) sv += w1[h*Cc+cc] * g_pooled[branch][b*Cc+cc];
        hdn[h] = fmaxf(sv, 0.f);
    }
    float lg[3];
    for (int si = 0; si < 3; si++) {
        int row = si*Cc + c;
        float sv = b2[row];
        for (int h = 0; h < 4; h++) sv += w2[row*4+h]*hdn[h];
        lg[si] = sv;
    }
    float mx = fmaxf(lg[0], fmaxf(lg[1], lg[2]));
    float e0 = __expf(lg[0]-mx), e1 = __expf(lg[1]-mx), e2 = __expf(lg[2]-mx);
    float inv = 1.f/(e0+e1+e2);
    g_wt[branch][(b*3+0)*Cc+c] = e0*inv;
    g_wt[branch][(b*3+1)*Cc+c] = e1*inv;
    g_wt[branch][(b*3+2)*Cc+c] = e2*inv;
}

__global__ void combine_kernel(float* __restrict__ out) {
    const size_t N1 = (size_t)Bq*Cc*HWp;
    size_t idx = (size_t)blockIdx.x*blockDim.x + threadIdx.x;
    if (idx >= 2*N1) return;
    int branch = (int)(idx / N1);
    size_t r = idx % N1;
    int b = (int)(r / ((size_t)Cc*HWp));
    int c = (int)((r / HWp) % Cc);
    float w0 = g_wt[branch][(b*3+0)*Cc+c];
    float w1 = g_wt[branch][(b*3+1)*Cc+c];
    float w2 = g_wt[branch][(b*3+2)*Cc+c];
    out[idx] = g_feats[branch][0][r]*w0 + g_feats[branch][1][r]*w1 + g_feats[branch][2][r]*w2;
}

// ---------------- host launch ----------------
extern "C" void kernel_launch(void* const* d_in, const int* in_sizes, int n_in,
                              void* d_out, int out_size) {
    const float *bg = nullptr, *tg = nullptr;
    const float *bg_mem[3] = {}, *tg_mem[3] = {};
    const float *temp_bg[3] = {}, *temp_tg[3] = {};
    const float *f1w[2] = {}, *f1b[2] = {}, *f2w[2] = {}, *f2b[2] = {};
    int n_img = 0, n_t = 0, n_f1w = 0, n_f1b = 0, n_f2w = 0, n_f2b = 0;

    for (int i = 0; i < n_in; i++) {
        const float* p = (const float*)d_in[i];
        switch (in_sizes[i]) {
            case Bq*Cc*HWp: if (n_img++ == 0) bg = p; else tg = p; break;
            case 64*144: bg_mem[0] = p; break;
            case 64*400: bg_mem[1] = p; break;
            case 64*784: bg_mem[2] = p; break;
            case 8*144:  tg_mem[0] = p; break;
            case 8*400:  tg_mem[1] = p; break;
            case 8*784:  tg_mem[2] = p; break;
            case 1: {   // temps interleave bg/tg per scale in setup_inputs order
                        // (all values identical = 10.0, so any ordering is equivalent)
                int k = n_t++;
                if (k < 6) { if (k % 2 == 0) temp_bg[k/2] = p; else temp_tg[k/2] = p; }
                break; }
            case 64:  { if (n_f1w < 2) f1w[n_f1w] = p; n_f1w++; break; }
            case 4:   { if (n_f1b < 2) f1b[n_f1b] = p; n_f1b++; break; }
            case 192: { if (n_f2w < 2) f2w[n_f2w] = p; n_f2w++; break; }
            case 48:  { if (n_f2b < 2) f2b[n_f2b] = p; n_f2b++; break; }
            default: break;
        }
    }

    // 1) transpose memories into FMA-friendly layouts
    transpose_mem_kernel<3,64><<<64,256>>>(bg_mem[0], 0);
    transpose_mem_kernel<5,64><<<64,256>>>(bg_mem[1], 1);
    transpose_mem_kernel<7,64><<<64,256>>>(bg_mem[2], 2);
    transpose_mem_kernel<3,8> <<<64,256>>>(tg_mem[0], 0);
    transpose_mem_kernel<5,8> <<<64,256>>>(tg_mem[1], 1);
    transpose_mem_kernel<7,8> <<<64,256>>>(tg_mem[2], 2);

    dim3 blk(16, 8);
    dim3 grd(Ww/16, Hh/8, Bq);

    // 2) sim + softmax -> att maps
    logits_kernel<3,64><<<grd, blk>>>(bg, temp_bg[0], 0);
    logits_kernel<5,64><<<grd, blk>>>(bg, temp_bg[1], 1);
    logits_kernel<7,64><<<grd, blk>>>(bg, temp_bg[2], 2);
    logits_kernel<3,8> <<<grd, blk>>>(tg, temp_tg[0], 0);
    logits_kernel<5,8> <<<grd, blk>>>(tg, temp_tg[1], 1);
    logits_kernel<7,8> <<<grd, blk>>>(tg, temp_tg[2], 2);

    // 3) readout + fold + divisor -> per-scale feats
    fold_kernel<3,64,8><<<grd, blk>>>(0);
    fold_kernel<5,64,8><<<grd, blk>>>(1);
    fold_kernel<7,64,8><<<grd, blk>>>(2);
    fold_kernel<3,8,8> <<<grd, blk>>>(0);
    fold_kernel<5,8,8> <<<grd, blk>>>(1);
    fold_kernel<7,8,8> <<<grd, blk>>>(2);

    // 4) fusion
    pool_kernel<<<2*Bq*Cc, 256>>>();
    fuse_wt_kernel<<<1, 64>>>(f1w[0], f1b[0], f2w[0], f2b[0],
                              f1w[1], f1b[1], f2w[1], f2b[1]);
    const size_t Ntot = (size_t)2*Bq*Cc*HWp;
    combine_kernel<<<(unsigned)((Ntot + 255)/256), 256>>>((float*)d_out);
}

// round 2
// speedup vs baseline: 1.1778x; 1.1778x over previous
#include <cuda_runtime.h>

#define Bq 2
#define Cc 16
#define Hh 128
#define Ww 128
#define HWp (Hh*Ww)
#define TX 32
#define TY 8
#define NT 256

// ---------------- static device scratch (no allocations) ----------------
__device__ float g_att_bg[3][(size_t)Bq*64*HWp];          // 24 MB
__device__ float g_att_tg[3][(size_t)Bq*8*HWp];           // 3 MB
__device__ float g_feats[2][3][(size_t)Bq*Cc*HWp];        // 12 MB
__device__ float g_pooled[2][Bq*Cc];
__device__ float g_wt[2][Bq*3*Cc];
// transposed memory copies:
//   A-layout: [c][d][m]   (m contiguous)  -> for logits kernel
//   B-layout: [m][d][c]   (c contiguous)  -> for fold kernel
__device__ float g_memA_bg[3][64*Cc*49];
__device__ float g_memA_tg[3][8*Cc*49];
__device__ float g_memB_bg[3][64*Cc*49];
__device__ float g_memB_tg[3][8*Cc*49];

// ---------------- fused mem transpose (all 6 memories, one launch) ----------------
__global__ void transpose_all_kernel(const float* __restrict__ bm0, const float* __restrict__ bm1,
                                     const float* __restrict__ bm2, const float* __restrict__ tm0,
                                     const float* __restrict__ tm1, const float* __restrict__ tm2) {
    int g = blockIdx.y;
    const float* src; float* A; float* Bm; int M; int PP;
    switch (g) {
        case 0: src = bm2; A = g_memA_bg[2]; Bm = g_memB_bg[2]; M = 64; PP = 49; break;
        case 1: src = bm1; A = g_memA_bg[1]; Bm = g_memB_bg[1]; M = 64; PP = 25; break;
        case 2: src = bm0; A = g_memA_bg[0]; Bm = g_memB_bg[0]; M = 64; PP = 9;  break;
        case 3: src = tm2; A = g_memA_tg[2]; Bm = g_memB_tg[2]; M = 8;  PP = 49; break;
        case 4: src = tm1; A = g_memA_tg[1]; Bm = g_memB_tg[1]; M = 8;  PP = 25; break;
        default:src = tm0; A = g_memA_tg[0]; Bm = g_memB_tg[0]; M = 8;  PP = 9;  break;
    }
    int n = M*Cc*PP;
    for (int idx = blockIdx.x*blockDim.x + threadIdx.x; idx < n; idx += gridDim.x*blockDim.x) {
        int m   = idx / (Cc*PP);
        int rem = idx % (Cc*PP);
        int c   = rem / PP;
        int d   = rem % PP;
        float v = src[idx];
        A[(c*PP + d)*M + m]   = v;
        Bm[(m*PP + d)*Cc + c] = v;
    }
}

// ---------------- logits + softmax body (implicit-GEMM sim) ----------------
// tile = 32x8 pixels, thread-per-pixel, M accumulators in registers.
template<int P, int M>
__device__ __forceinline__ void logits_body(float* __restrict__ sb,
                                            const float* __restrict__ x,
                                            const float* __restrict__ memA,
                                            float* __restrict__ att,
                                            const float* __restrict__ temp,
                                            int b, int x0, int y0) {
    constexpr int PAD = P/2;
    constexpr int SW = TX + P - 1, SH = TY + P - 1;
    constexpr int PP = P*P;
    float* xs = sb;                   // [Cc][SH][SW]
    float* ms = sb + Cc*SH*SW;        // [PP][M], m contiguous

    const int t  = threadIdx.x;
    const int tx = t & 31, ty = t >> 5;

    // load x tile with halo (zero-padded)
    for (int idx = t; idx < Cc*SH*SW; idx += NT) {
        int c = idx / (SH*SW);
        int r = idx % (SH*SW);
        int ry = r / SW, rx = r % SW;
        int gy = y0 + ry - PAD, gx = x0 + rx - PAD;
        float v = 0.f;
        if (gy >= 0 && gy < Hh && gx >= 0 && gx < Ww)
            v = x[((size_t)(b*Cc + c)*Hh + gy)*Ww + gx];
        xs[idx] = v;
    }

    float acc[M];
    #pragma unroll
    for (int m = 0; m < M; m++) acc[m] = 0.f;

    for (int c = 0; c < Cc; c++) {
        __syncthreads();
        {   // stage this channel's memory chunk [PP][M] (vectorized, coalesced)
            const float4* src4 = reinterpret_cast<const float4*>(memA + (size_t)c*PP*M);
            float4* dst4 = reinterpret_cast<float4*>(ms);
            for (int idx = t; idx < PP*M/4; idx += NT) dst4[idx] = src4[idx];
        }
        __syncthreads();
        const float* xc = xs + c*SH*SW;
        for (int i = 0; i < P; i++) {
            for (int j = 0; j < P; j++) {
                float xv = xc[(ty + i)*SW + tx + j];
                const float4* mp = reinterpret_cast<const float4*>(ms + (i*P + j)*M);
                #pragma unroll
                for (int m4 = 0; m4 < M/4; m4++) {
                    float4 w = mp[m4];
                    acc[4*m4+0] = fmaf(xv, w.x, acc[4*m4+0]);
                    acc[4*m4+1] = fmaf(xv, w.y, acc[4*m4+1]);
                    acc[4*m4+2] = fmaf(xv, w.z, acc[4*m4+2]);
                    acc[4*m4+3] = fmaf(xv, w.w, acc[4*m4+3]);
                }
            }
        }
    }

    // softmax over M (scale = temp / sqrt(D))
    float scale = temp[0] / sqrtf((float)(Cc*PP));
    float mx = acc[0];
    #pragma unroll
    for (int m = 1; m < M; m++) mx = fmaxf(mx, acc[m]);
    float ssum = 0.f;
    #pragma unroll
    for (int m = 0; m < M; m++) { acc[m] = __expf(scale*(acc[m]-mx)); ssum += acc[m]; }
    float inv = 1.f / ssum;

    int gy = y0 + ty, gx = x0 + tx;
    #pragma unroll
    for (int m = 0; m < M; m++)
        att[((size_t)(b*M + m)*Hh + gy)*Ww + gx] = acc[m]*inv;
}

static constexpr int LOGITS_SB = 16*14*38 + 49*64;  // p=7,M=64 worst case = 11648 floats

// one launch covers all 6 (branch,scale) groups; heaviest groups first
__global__ __launch_bounds__(NT) void logits_all_kernel(
    const float* __restrict__ bg, const float* __restrict__ tg,
    const float* __restrict__ tb7, const float* __restrict__ tb5, const float* __restrict__ tb3,
    const float* __restrict__ tt7, const float* __restrict__ tt5, const float* __restrict__ tt3) {
    __shared__ __align__(16) float sb[LOGITS_SB];
    int blk = blockIdx.x;
    int group = blk >> 7;       // 128 blocks per group (2 batches x 64 tiles)
    int r = blk & 127;
    int b = r >> 6;
    int tt = r & 63;
    int x0 = (tt & 3)*TX, y0 = (tt >> 2)*TY;
    switch (group) {
        case 0: logits_body<7,64>(sb, bg, g_memA_bg[2], g_att_bg[2], tb7, b, x0, y0); break;
        case 1: logits_body<5,64>(sb, bg, g_memA_bg[1], g_att_bg[1], tb5, b, x0, y0); break;
        case 2: logits_body<3,64>(sb, bg, g_memA_bg[0], g_att_bg[0], tb3, b, x0, y0); break;
        case 3: logits_body<7,8> (sb, tg, g_memA_tg[2], g_att_tg[2], tt7, b, x0, y0); break;
        case 4: logits_body<5,8> (sb, tg, g_memA_tg[1], g_att_tg[1], tt5, b, x0, y0); break;
        default:logits_body<3,8> (sb, tg, g_memA_tg[0], g_att_tg[0], tt3, b, x0, y0); break;
    }
}

// ---------------- readout + fold body (transposed-conv over att maps) ----------------
template<int P, int M, int MC>
__device__ __forceinline__ void fold_body(float* __restrict__ sb,
                                          const float* __restrict__ att,
                                          const float* __restrict__ memB,
                                          float* __restrict__ feat,
                                          int b, int x0, int y0) {
    constexpr int PAD = P/2;
    constexpr int SW = TX + P - 1, SH = TY + P - 1;
    constexpr int PP = P*P;
    float* as_ = sb;                   // [MC][SH][SW]
    float* msB = sb + MC*SH*SW;        // [MC][PP][Cc], c contiguous

    const int t  = threadIdx.x;
    const int tx = t & 31, ty = t >> 5;

    float acc[Cc];
    #pragma unroll
    for (int c = 0; c < Cc; c++) acc[c] = 0.f;

    for (int m0 = 0; m0 < M; m0 += MC) {
        __syncthreads();
        for (int idx = t; idx < MC*SH*SW; idx += NT) {
            int ml = idx/(SH*SW); int r = idx%(SH*SW);
            int ry = r/SW, rx = r%SW;
            int gy = y0+ry-PAD, gx = x0+rx-PAD;
            float v = 0.f;
            if (gy >= 0 && gy < Hh && gx >= 0 && gx < Ww)
                v = att[((size_t)(b*M + m0+ml)*Hh + gy)*Ww + gx];
            as_[idx] = v;
        }
        {
            const float4* src4 = reinterpret_cast<const float4*>(memB + (size_t)m0*PP*Cc);
            float4* dst4 = reinterpret_cast<float4*>(msB);
            for (int idx = t; idx < MC*PP*Cc/4; idx += NT) dst4[idx] = src4[idx];
        }
        __syncthreads();
        for (int ml = 0; ml < MC; ml++) {
            const float* am = as_ + ml*SH*SW;
            for (int i = 0; i < P; i++) {
                for (int j = 0; j < P; j++) {
                    float av = am[(ty + (P-1-i))*SW + tx + (P-1-j)];
                    const float4* mp = reinterpret_cast<const float4*>(msB + (ml*PP + i*P + j)*Cc);
                    #pragma unroll
                    for (int c4 = 0; c4 < Cc/4; c4++) {
                        float4 w = mp[c4];
                        acc[4*c4+0] = fmaf(av, w.x, acc[4*c4+0]);
                        acc[4*c4+1] = fmaf(av, w.y, acc[4*c4+1]);
                        acc[4*c4+2] = fmaf(av, w.z, acc[4*c4+2]);
                        acc[4*c4+3] = fmaf(av, w.w, acc[4*c4+3]);
                    }
                }
            }
        }
    }

    int gy = y0+ty, gx = x0+tx;
    int cy = min(gy,PAD) + min(Hh-1-gy,PAD) + 1;   // analytic fold-of-ones divisor
    int cx = min(gx,PAD) + min(Ww-1-gx,PAD) + 1;
    float invd = 1.f/((float)(cy*cx) + 1e-8f);
    #pragma unroll
    for (int c = 0; c < Cc; c++)
        feat[((size_t)(b*Cc+c)*Hh+gy)*Ww+gx] = acc[c]*invd;
}

static constexpr int FOLD_SB = 8*14*38 + 8*49*16;   // p=7,MC=8 worst case = 10528 floats

__global__ __launch_bounds__(NT) void fold_all_kernel() {
    __shared__ __align__(16) float sb[FOLD_SB];
    int blk = blockIdx.x;
    int group = blk >> 7;
    int r = blk & 127;
    int b = r >> 6;
    int tt = r & 63;
    int x0 = (tt & 3)*TX, y0 = (tt >> 2)*TY;
    switch (group) {
        case 0: fold_body<7,64,8>(sb, g_att_bg[2], g_memB_bg[2], g_feats[0][2], b, x0, y0); break;
        case 1: fold_body<5,64,8>(sb, g_att_bg[1], g_memB_bg[1], g_feats[0][1], b, x0, y0); break;
        case 2: fold_body<3,64,8>(sb, g_att_bg[0], g_memB_bg[0], g_feats[0][0], b, x0, y0); break;
        case 3: fold_body<7,8,8> (sb, g_att_tg[2], g_memB_tg[2], g_feats[1][2], b, x0, y0); break;
        case 4: fold_body<5,8,8> (sb, g_att_tg[1], g_memB_tg[1], g_feats[1][1], b, x0, y0); break;
        default:fold_body<3,8,8> (sb, g_att_tg[0], g_memB_tg[0], g_feats[1][0], b, x0, y0); break;
    }
}

// ---------------- fusion ----------------
__global__ void pool_kernel() {
    int bi = blockIdx.x;                // 0..63
    int branch = bi >> 5;               // Bq*Cc = 32
    int r = bi & 31;
    const float* f0 = g_feats[branch][0] + (size_t)r*HWp;
    const float* f1 = g_feats[branch][1] + (size_t)r*HWp;
    const float* f2 = g_feats[branch][2] + (size_t)r*HWp;
    float sv = 0.f;
    for (int i = threadIdx.x; i < HWp; i += blockDim.x)
        sv += f0[i] + f1[i] + f2[i];
    __shared__ float red[256];
    red[threadIdx.x] = sv;
    __syncthreads();
    for (int off = 128; off > 0; off >>= 1) {
        if (threadIdx.x < off) red[threadIdx.x] += red[threadIdx.x + off];
        __syncthreads();
    }
    if (threadIdx.x == 0) g_pooled[branch][r] = red[0] / (float)HWp;
}

__global__ void fuse_wt_kernel(const float* __restrict__ bw1, const float* __restrict__ bb1,
                               const float* __restrict__ bw2, const float* __restrict__ bb2,
                               const float* __restrict__ tw1, const float* __restrict__ tb1,
                               const float* __restrict__ tw2, const float* __restrict__ tb2) {
    int t = threadIdx.x;
    if (t >= 2*Bq*Cc) return;
    int branch = t / (Bq*Cc);
    int r = t % (Bq*Cc);
    int b = r / Cc, c = r % Cc;
    const float* w1 = branch ? tw1 : bw1;
    const float* b1 = branch ? tb1 : bb1;
    const float* w2 = branch ? tw2 : bw2;
    const float* b2 = branch ? tb2 : bb2;
    float hdn[4];
    for (int h = 0; h < 4; h++) {
        float sv = b1[h];
        for (int cc = 0; cc < Cc; cc++) sv += w1[h*Cc+cc] * g_pooled[branch][b*Cc+cc];
        hdn[h] = fmaxf(sv, 0.f);
    }
    float lg[3];
    for (int si = 0; si < 3; si++) {
        int row = si*Cc + c;
        float sv = b2[row];
        for (int h = 0; h < 4; h++) sv += w2[row*4+h]*hdn[h];
        lg[si] = sv;
    }
    float mx = fmaxf(lg[0], fmaxf(lg[1], lg[2]));
    float e0 = __expf(lg[0]-mx), e1 = __expf(lg[1]-mx), e2 = __expf(lg[2]-mx);
    float inv = 1.f/(e0+e1+e2);
    g_wt[branch][(b*3+0)*Cc+c] = e0*inv;
    g_wt[branch][(b*3+1)*Cc+c] = e1*inv;
    g_wt[branch][(b*3+2)*Cc+c] = e2*inv;
}

__global__ void combine_kernel(float* __restrict__ out) {
    const size_t N1 = (size_t)Bq*Cc*HWp;
    size_t idx = (size_t)blockIdx.x*blockDim.x + threadIdx.x;
    if (idx >= 2*N1) return;
    int branch = (int)(idx / N1);
    size_t r = idx % N1;
    int b = (int)(r / ((size_t)Cc*HWp));
    int c = (int)((r / HWp) % Cc);
    float w0 = g_wt[branch][(b*3+0)*Cc+c];
    float w1 = g_wt[branch][(b*3+1)*Cc+c];
    float w2 = g_wt[branch][(b*3+2)*Cc+c];
    out[idx] = g_feats[branch][0][r]*w0 + g_feats[branch][1][r]*w1 + g_feats[branch][2][r]*w2;
}

// ---------------- host launch ----------------
extern "C" void kernel_launch(void* const* d_in, const int* in_sizes, int n_in,
                              void* d_out, int out_size) {
    const float *bg = nullptr, *tg = nullptr;
    const float *bg_mem[3] = {}, *tg_mem[3] = {};
    const float *temp_bg[3] = {}, *temp_tg[3] = {};
    const float *f1w[2] = {}, *f1b[2] = {}, *f2w[2] = {}, *f2b[2] = {};
    int n_img = 0, n_t = 0, n_f1w = 0, n_f1b = 0, n_f2w = 0, n_f2b = 0;

    for (int i = 0; i < n_in; i++) {
        const float* p = (const float*)d_in[i];
        switch (in_sizes[i]) {
            case Bq*Cc*HWp: if (n_img++ == 0) bg = p; else tg = p; break;
            case 64*144: bg_mem[0] = p; break;
            case 64*400: bg_mem[1] = p; break;
            case 64*784: bg_mem[2] = p; break;
            case 8*144:  tg_mem[0] = p; break;
            case 8*400:  tg_mem[1] = p; break;
            case 8*784:  tg_mem[2] = p; break;
            case 1: {   // all temps are identical (10.0), ordering-immune
                int k = n_t++;
                if (k < 6) { if (k % 2 == 0) temp_bg[k/2] = p; else temp_tg[k/2] = p; }
                break; }
            case 64:  { if (n_f1w < 2) f1w[n_f1w] = p; n_f1w++; break; }
            case 4:   { if (n_f1b < 2) f1b[n_f1b] = p; n_f1b++; break; }
            case 192: { if (n_f2w < 2) f2w[n_f2w] = p; n_f2w++; break; }
            case 48:  { if (n_f2b < 2) f2b[n_f2b] = p; n_f2b++; break; }
            default: break;
        }
    }

    // 1) transpose all memories (one launch)
    transpose_all_kernel<<<dim3(16,6), 256>>>(bg_mem[0], bg_mem[1], bg_mem[2],
                                              tg_mem[0], tg_mem[1], tg_mem[2]);

    // 2) sim + softmax -> att maps (one fused launch, 768 blocks, heavy first)
    logits_all_kernel<<<768, NT>>>(bg, tg,
                                   temp_bg[2], temp_bg[1], temp_bg[0],
                                   temp_tg[2], temp_tg[1], temp_tg[0]);

    // 3) readout + fold + divisor -> per-scale feats (one fused launch)
    fold_all_kernel<<<768, NT>>>();

    // 4) fusion
    pool_kernel<<<2*Bq*Cc, 256>>>();
    fuse_wt_kernel<<<1, 64>>>(f1w[0], f1b[0], f2w[0], f2b[0],
                              f1w[1], f1b[1], f2w[1], f2b[1]);
    const size_t Ntot = (size_t)2*Bq*Cc*HWp;
    combine_kernel<<<(unsigned)((Ntot + 255)/256), 256>>>((float*)d_out);
}

// round 3
// speedup vs baseline: 1.2203x; 1.0361x over previous
#include <cuda_runtime.h>

#define Bq 2
#define Cc 16
#define Hh 128
#define Ww 128
#define HWp (Hh*Ww)
#define TX 32
#define TY 8
#define NT 256

// ---------------- static device scratch (no allocations) ----------------
__device__ float g_att_bg[3][(size_t)Bq*64*HWp];          // 24 MB
__device__ float g_att_tg[3][(size_t)Bq*8*HWp];           // 3 MB
__device__ float g_feats[2][3][(size_t)Bq*Cc*HWp];        // 12 MB
__device__ float g_pooled[2][Bq*Cc];
__device__ float g_wt[2][Bq*3*Cc];
// transposed memory copies:
//   A-layout: [c][d][m]   (m contiguous)  -> for logits
//   B-layout: [m][d][c]   (c contiguous)  -> for fold
__device__ float g_memA_bg[3][64*Cc*49];
__device__ float g_memA_tg[3][8*Cc*49];
__device__ float g_memB_bg[3][64*Cc*49];
__device__ float g_memB_tg[3][8*Cc*49];

// ---------------- fused mem transpose (all 6 memories, one launch) ----------------
__global__ void transpose_all_kernel(const float* __restrict__ bm0, const float* __restrict__ bm1,
                                     const float* __restrict__ bm2, const float* __restrict__ tm0,
                                     const float* __restrict__ tm1, const float* __restrict__ tm2) {
    int g = blockIdx.y;
    const float* src; float* A; float* Bm; int M; int PP;
    switch (g) {
        case 0: src = bm2; A = g_memA_bg[2]; Bm = g_memB_bg[2]; M = 64; PP = 49; break;
        case 1: src = bm1; A = g_memA_bg[1]; Bm = g_memB_bg[1]; M = 64; PP = 25; break;
        case 2: src = bm0; A = g_memA_bg[0]; Bm = g_memB_bg[0]; M = 64; PP = 9;  break;
        case 3: src = tm2; A = g_memA_tg[2]; Bm = g_memB_tg[2]; M = 8;  PP = 49; break;
        case 4: src = tm1; A = g_memA_tg[1]; Bm = g_memB_tg[1]; M = 8;  PP = 25; break;
        default:src = tm0; A = g_memA_tg[0]; Bm = g_memB_tg[0]; M = 8;  PP = 9;  break;
    }
    int n = M*Cc*PP;
    for (int idx = blockIdx.x*blockDim.x + threadIdx.x; idx < n; idx += gridDim.x*blockDim.x) {
        int m   = idx / (Cc*PP);
        int rem = idx % (Cc*PP);
        int c   = rem / PP;
        int d   = rem % PP;
        float v = src[idx];
        A[(c*PP + d)*M + m]   = v;
        Bm[(m*PP + d)*Cc + c] = v;
    }
}

// ================= BG logits: 4 pixels x 16 m per thread, row-register reuse =================
// tile 32x8; threads = 32 tx * 2 y-groups * 4 m-groups(16 m each). warp-uniform m-group.
template<int P>
__device__ __forceinline__ void logits_bg_body(float* __restrict__ sb,
                                               const float* __restrict__ x,
                                               const float* __restrict__ memA,
                                               float* __restrict__ att,
                                               const float* __restrict__ temp,
                                               int b, int x0, int y0) {
    constexpr int PAD = P/2;
    constexpr int SW = TX + P - 1, SH = TY + P - 1;
    constexpr int PP = P*P;
    float* xs = sb;                 // [Cc][SH][SW]
    float* ms = sb + Cc*SH*SW;      // [PP][64]

    const int t  = threadIdx.x;
    const int tx = t & 31;
    const int w  = t >> 5;          // warp id 0..7
    const int tyg = w & 1;          // y group (rows tyg*4 .. +3)
    const int mg  = w >> 1;         // m group (16 m's)
    const int ty0 = tyg*4;

    // stage x tile with halo (zero-padded)
    for (int idx = t; idx < Cc*SH*SW; idx += NT) {
        int c = idx / (SH*SW);
        int r = idx % (SH*SW);
        int ry = r / SW, rx = r % SW;
        int gy = y0 + ry - PAD, gx = x0 + rx - PAD;
        float v = 0.f;
        if (gy >= 0 && gy < Hh && gx >= 0 && gx < Ww)
            v = x[((size_t)(b*Cc + c)*Hh + gy)*Ww + gx];
        xs[idx] = v;
    }

    float acc[64];
    #pragma unroll
    for (int q = 0; q < 64; q++) acc[q] = 0.f;

    for (int c = 0; c < Cc; c++) {
        __syncthreads();
        {   // stage this channel's memory chunk [PP][64]
            const float4* s4 = reinterpret_cast<const float4*>(memA + (size_t)c*PP*64);
            float4* d4 = reinterpret_cast<float4*>(ms);
            for (int idx = t; idx < PP*16; idx += NT) d4[idx] = s4[idx];
        }
        __syncthreads();
        const float* xc = xs + c*SH*SW;
        #pragma unroll 1
        for (int j = 0; j < P; j++) {
            float xr[P+3];
            #pragma unroll
            for (int r = 0; r < P+3; r++) xr[r] = xc[(ty0 + r)*SW + tx + j];
            #pragma unroll
            for (int i = 0; i < P; i++) {
                const float4* mp = reinterpret_cast<const float4*>(ms + (i*P + j)*64 + mg*16);
                float4 w0 = mp[0], w1 = mp[1], w2 = mp[2], w3 = mp[3];
                #pragma unroll
                for (int k = 0; k < 4; k++) {
                    float xv = xr[i + k];
                    float* a = acc + k*16;
                    a[0]  = fmaf(xv, w0.x, a[0]);  a[1]  = fmaf(xv, w0.y, a[1]);
                    a[2]  = fmaf(xv, w0.z, a[2]);  a[3]  = fmaf(xv, w0.w, a[3]);
                    a[4]  = fmaf(xv, w1.x, a[4]);  a[5]  = fmaf(xv, w1.y, a[5]);
                    a[6]  = fmaf(xv, w1.z, a[6]);  a[7]  = fmaf(xv, w1.w, a[7]);
                    a[8]  = fmaf(xv, w2.x, a[8]);  a[9]  = fmaf(xv, w2.y, a[9]);
                    a[10] = fmaf(xv, w2.z, a[10]); a[11] = fmaf(xv, w2.w, a[11]);
                    a[12] = fmaf(xv, w3.x, a[12]); a[13] = fmaf(xv, w3.y, a[13]);
                    a[14] = fmaf(xv, w3.z, a[14]); a[15] = fmaf(xv, w3.w, a[15]);
                }
            }
        }
    }

    // softmax over 64 m (reduce across 4 m-groups via smem)
    float scale = temp[0] / sqrtf((float)(Cc*PP));
    __syncthreads();                 // done reading xs/ms; reuse xs as reduction buffer
    float* red  = xs;                // [4 mg][8 rows][32 tx]
    float* red2 = xs + 1024;
    #pragma unroll
    for (int k = 0; k < 4; k++) {
        float mx = acc[k*16];
        #pragma unroll
        for (int m = 1; m < 16; m++) mx = fmaxf(mx, acc[k*16 + m]);
        red[(mg*8 + ty0 + k)*32 + tx] = mx;
    }
    __syncthreads();
    float gsum[4];
    #pragma unroll
    for (int k = 0; k < 4; k++) {
        int row = (ty0 + k)*32 + tx;
        float mx = fmaxf(fmaxf(red[row], red[256 + row]), fmaxf(red[512 + row], red[768 + row]));
        float s = 0.f;
        #pragma unroll
        for (int m = 0; m < 16; m++) {
            acc[k*16 + m] = __expf(scale*(acc[k*16 + m] - mx));
            s += acc[k*16 + m];
        }
        red2[(mg*8 + ty0 + k)*32 + tx] = s;
        gsum[k] = s;   // placeholder; final below
    }
    __syncthreads();
    #pragma unroll
    for (int k = 0; k < 4; k++) {
        int row = (ty0 + k)*32 + tx;
        float s = red2[row] + red2[256 + row] + red2[512 + row] + red2[768 + row];
        float inv = 1.f / s;
        int gy = y0 + ty0 + k, gx = x0 + tx;
        #pragma unroll
        for (int m = 0; m < 16; m++)
            att[((size_t)(b*64 + mg*16 + m)*Hh + gy)*Ww + gx] = acc[k*16 + m]*inv;
    }
    (void)gsum;
}

// ================= TG logits (M=8): round-2 body =================
template<int P, int M>
__device__ __forceinline__ void logits_tg_body(float* __restrict__ sb,
                                               const float* __restrict__ x,
                                               const float* __restrict__ memA,
                                               float* __restrict__ att,
                                               const float* __restrict__ temp,
                                               int b, int x0, int y0) {
    constexpr int PAD = P/2;
    constexpr int SW = TX + P - 1, SH = TY + P - 1;
    constexpr int PP = P*P;
    float* xs = sb;
    float* ms = sb + Cc*SH*SW;
    const int t  = threadIdx.x;
    const int tx = t & 31, ty = t >> 5;

    for (int idx = t; idx < Cc*SH*SW; idx += NT) {
        int c = idx / (SH*SW);
        int r = idx % (SH*SW);
        int ry = r / SW, rx = r % SW;
        int gy = y0 + ry - PAD, gx = x0 + rx - PAD;
        float v = 0.f;
        if (gy >= 0 && gy < Hh && gx >= 0 && gx < Ww)
            v = x[((size_t)(b*Cc + c)*Hh + gy)*Ww + gx];
        xs[idx] = v;
    }

    float acc[M];
    #pragma unroll
    for (int m = 0; m < M; m++) acc[m] = 0.f;

    for (int c = 0; c < Cc; c++) {
        __syncthreads();
        {
            const float4* s4 = reinterpret_cast<const float4*>(memA + (size_t)c*PP*M);
            float4* d4 = reinterpret_cast<float4*>(ms);
            for (int idx = t; idx < PP*M/4; idx += NT) d4[idx] = s4[idx];
        }
        __syncthreads();
        const float* xc = xs + c*SH*SW;
        for (int i = 0; i < P; i++) {
            for (int j = 0; j < P; j++) {
                float xv = xc[(ty + i)*SW + tx + j];
                const float4* mp = reinterpret_cast<const float4*>(ms + (i*P + j)*M);
                #pragma unroll
                for (int m4 = 0; m4 < M/4; m4++) {
                    float4 w = mp[m4];
                    acc[4*m4+0] = fmaf(xv, w.x, acc[4*m4+0]);
                    acc[4*m4+1] = fmaf(xv, w.y, acc[4*m4+1]);
                    acc[4*m4+2] = fmaf(xv, w.z, acc[4*m4+2]);
                    acc[4*m4+3] = fmaf(xv, w.w, acc[4*m4+3]);
                }
            }
        }
    }

    float scale = temp[0] / sqrtf((float)(Cc*PP));
    float mx = acc[0];
    #pragma unroll
    for (int m = 1; m < M; m++) mx = fmaxf(mx, acc[m]);
    float ssum = 0.f;
    #pragma unroll
    for (int m = 0; m < M; m++) { acc[m] = __expf(scale*(acc[m]-mx)); ssum += acc[m]; }
    float inv = 1.f / ssum;

    int gy = y0 + ty, gx = x0 + tx;
    #pragma unroll
    for (int m = 0; m < M; m++)
        att[((size_t)(b*M + m)*Hh + gy)*Ww + gx] = acc[m]*inv;
}

static constexpr int LOGITS_SB = 16*14*38 + 49*64;  // p=7 bg worst case = 11648 floats

__global__ __launch_bounds__(NT) void logits_all_kernel(
    const float* __restrict__ bg, const float* __restrict__ tg,
    const float* __restrict__ tb7, const float* __restrict__ tb5, const float* __restrict__ tb3,
    const float* __restrict__ tt7, const float* __restrict__ tt5, const float* __restrict__ tt3) {
    __shared__ __align__(16) float sb[LOGITS_SB];
    int blk = blockIdx.x;
    int group = blk >> 7;       // 128 blocks per group
    int r = blk & 127;
    int b = r >> 6;
    int tt = r & 63;
    int x0 = (tt & 3)*TX, y0 = (tt >> 2)*TY;
    switch (group) {
        case 0: logits_bg_body<7>(sb, bg, g_memA_bg[2], g_att_bg[2], tb7, b, x0, y0); break;
        case 1: logits_bg_body<5>(sb, bg, g_memA_bg[1], g_att_bg[1], tb5, b, x0, y0); break;
        case 2: logits_bg_body<3>(sb, bg, g_memA_bg[0], g_att_bg[0], tb3, b, x0, y0); break;
        case 3: logits_tg_body<7,8>(sb, tg, g_memA_tg[2], g_att_tg[2], tt7, b, x0, y0); break;
        case 4: logits_tg_body<5,8>(sb, tg, g_memA_tg[1], g_att_tg[1], tt5, b, x0, y0); break;
        default:logits_tg_body<3,8>(sb, tg, g_memA_tg[0], g_att_tg[0], tt3, b, x0, y0); break;
    }
}

// ================= BG fold: 32x32 tile, 4 pixels x 16 c per thread =================
template<int P>
__device__ __forceinline__ void fold_bg_body(float* __restrict__ sb,
                                             const float* __restrict__ att,
                                             const float* __restrict__ memB,
                                             float* __restrict__ feat,
                                             int b, int x0, int y0) {
    constexpr int PAD = P/2;
    constexpr int TW = 32, TH = 32;
    constexpr int SW2 = TW + P - 1, SH2 = TH + P - 1;
    constexpr int PP = P*P;
    constexpr int MC = 4;
    float* as_ = sb;                    // [MC][SH2][SW2]
    float* msB = sb + MC*SH2*SW2;       // [MC][PP][16]

    const int t  = threadIdx.x;
    const int tx = t & 31;
    const int tyg = t >> 5;             // 0..7, rows tyg*4..+3
    const int ty0 = tyg*4;

    float acc[64];
    #pragma unroll
    for (int q = 0; q < 64; q++) acc[q] = 0.f;

    for (int m0 = 0; m0 < 64; m0 += MC) {
        __syncthreads();
        for (int idx = t; idx < MC*SH2*SW2; idx += NT) {
            int ml = idx/(SH2*SW2); int r = idx%(SH2*SW2);
            int ry = r/SW2, rx = r%SW2;
            int gy = y0 + ry - PAD, gx = x0 + rx - PAD;
            float v = 0.f;
            if (gy >= 0 && gy < Hh && gx >= 0 && gx < Ww)
                v = att[((size_t)(b*64 + m0 + ml)*Hh + gy)*Ww + gx];
            as_[idx] = v;
        }
        {
            const float4* s4 = reinterpret_cast<const float4*>(memB + (size_t)m0*PP*16);
            float4* d4 = reinterpret_cast<float4*>(msB);
            for (int idx = t; idx < MC*PP*4; idx += NT) d4[idx] = s4[idx];
        }
        __syncthreads();
        #pragma unroll
        for (int ml = 0; ml < MC; ml++) {
            const float* am = as_ + ml*SH2*SW2;
            const float* mb = msB + ml*PP*16;
            #pragma unroll 1
            for (int j = 0; j < P; j++) {
                float ar[P+3];
                #pragma unroll
                for (int r = 0; r < P+3; r++) ar[r] = am[(ty0 + r)*SW2 + tx + j];
                #pragma unroll
                for (int i = 0; i < P; i++) {
                    const float4* mp = reinterpret_cast<const float4*>(mb + ((P-1-i)*P + (P-1-j))*16);
                    float4 w0 = mp[0], w1 = mp[1], w2 = mp[2], w3 = mp[3];
                    #pragma unroll
                    for (int k = 0; k < 4; k++) {
                        float av = ar[i + k];
                        float* a = acc + k*16;
                        a[0]  = fmaf(av, w0.x, a[0]);  a[1]  = fmaf(av, w0.y, a[1]);
                        a[2]  = fmaf(av, w0.z, a[2]);  a[3]  = fmaf(av, w0.w, a[3]);
                        a[4]  = fmaf(av, w1.x, a[4]);  a[5]  = fmaf(av, w1.y, a[5]);
                        a[6]  = fmaf(av, w1.z, a[6]);  a[7]  = fmaf(av, w1.w, a[7]);
                        a[8]  = fmaf(av, w2.x, a[8]);  a[9]  = fmaf(av, w2.y, a[9]);
                        a[10] = fmaf(av, w2.z, a[10]); a[11] = fmaf(av, w2.w, a[11]);
                        a[12] = fmaf(av, w3.x, a[12]); a[13] = fmaf(av, w3.y, a[13]);
                        a[14] = fmaf(av, w3.z, a[14]); a[15] = fmaf(av, w3.w, a[15]);
                    }
                }
            }
        }
    }

    #pragma unroll
    for (int k = 0; k < 4; k++) {
        int gy = y0 + ty0 + k, gx = x0 + tx;
        int cy = min(gy,PAD) + min(Hh-1-gy,PAD) + 1;
        int cx = min(gx,PAD) + min(Ww-1-gx,PAD) + 1;
        float invd = 1.f/((float)(cy*cx) + 1e-8f);
        #pragma unroll
        for (int c = 0; c < Cc; c++)
            feat[((size_t)(b*Cc + c)*Hh + gy)*Ww + gx] = acc[k*16 + c]*invd;
    }
}

// ================= TG fold (M=8): round-2 body =================
template<int P, int M, int MC>
__device__ __forceinline__ void fold_tg_body(float* __restrict__ sb,
                                             const float* __restrict__ att,
                                             const float* __restrict__ memB,
                                             float* __restrict__ feat,
                                             int b, int x0, int y0) {
    constexpr int PAD = P/2;
    constexpr int SW = TX + P - 1, SH = TY + P - 1;
    constexpr int PP = P*P;
    float* as_ = sb;
    float* msB = sb + MC*SH*SW;
    const int t  = threadIdx.x;
    const int tx = t & 31, ty = t >> 5;

    float acc[Cc];
    #pragma unroll
    for (int c = 0; c < Cc; c++) acc[c] = 0.f;

    for (int m0 = 0; m0 < M; m0 += MC) {
        __syncthreads();
        for (int idx = t; idx < MC*SH*SW; idx += NT) {
            int ml = idx/(SH*SW); int r = idx%(SH*SW);
            int ry = r/SW, rx = r%SW;
            int gy = y0+ry-PAD, gx = x0+rx-PAD;
            float v = 0.f;
            if (gy >= 0 && gy < Hh && gx >= 0 && gx < Ww)
                v = att[((size_t)(b*M + m0+ml)*Hh + gy)*Ww + gx];
            as_[idx] = v;
        }
        {
            const float4* s4 = reinterpret_cast<const float4*>(memB + (size_t)m0*PP*Cc);
            float4* d4 = reinterpret_cast<float4*>(msB);
            for (int idx = t; idx < MC*PP*Cc/4; idx += NT) d4[idx] = s4[idx];
        }
        __syncthreads();
        for (int ml = 0; ml < MC; ml++) {
            const float* am = as_ + ml*SH*SW;
            for (int i = 0; i < P; i++) {
                for (int j = 0; j < P; j++) {
                    float av = am[(ty + (P-1-i))*SW + tx + (P-1-j)];
                    const float4* mp = reinterpret_cast<const float4*>(msB + (ml*PP + i*P + j)*Cc);
                    #pragma unroll
                    for (int c4 = 0; c4 < Cc/4; c4++) {
                        float4 w = mp[c4];
                        acc[4*c4+0] = fmaf(av, w.x, acc[4*c4+0]);
                        acc[4*c4+1] = fmaf(av, w.y, acc[4*c4+1]);
                        acc[4*c4+2] = fmaf(av, w.z, acc[4*c4+2]);
                        acc[4*c4+3] = fmaf(av, w.w, acc[4*c4+3]);
                    }
                }
            }
        }
    }

    int gy = y0+ty, gx = x0+tx;
    int cy = min(gy,PAD) + min(Hh-1-gy,PAD) + 1;
    int cx = min(gx,PAD) + min(Ww-1-gx,PAD) + 1;
    float invd = 1.f/((float)(cy*cx) + 1e-8f);
    #pragma unroll
    for (int c = 0; c < Cc; c++)
        feat[((size_t)(b*Cc+c)*Hh+gy)*Ww+gx] = acc[c]*invd;
}

static constexpr int FOLD_SB = 8*14*38 + 8*49*16;   // tg p=7 worst = 10528 floats

__global__ __launch_bounds__(NT) void fold_all_kernel() {
    __shared__ __align__(16) float sb[FOLD_SB];
    int blk = blockIdx.x;
    if (blk < 96) {                       // bg: 32 blocks per scale (32x32 tiles)
        int group = blk >> 5;
        int r = blk & 31;
        int b = r >> 4;
        int tt = r & 15;
        int x0 = (tt & 3)*32, y0 = (tt >> 2)*32;
        switch (group) {
            case 0: fold_bg_body<7>(sb, g_att_bg[2], g_memB_bg[2], g_feats[0][2], b, x0, y0); break;
            case 1: fold_bg_body<5>(sb, g_att_bg[1], g_memB_bg[1], g_feats[0][1], b, x0, y0); break;
            default:fold_bg_body<3>(sb, g_att_bg[0], g_memB_bg[0], g_feats[0][0], b, x0, y0); break;
        }
    } else {                              // tg: 128 blocks per scale (32x8 tiles)
        int bb = blk - 96;
        int group = bb >> 7;
        int r = bb & 127;
        int b = r >> 6;
        int tt = r & 63;
        int x0 = (tt & 3)*TX, y0 = (tt >> 2)*TY;
        switch (group) {
            case 0: fold_tg_body<7,8,8>(sb, g_att_tg[2], g_memB_tg[2], g_feats[1][2], b, x0, y0); break;
            case 1: fold_tg_body<5,8,8>(sb, g_att_tg[1], g_memB_tg[1], g_feats[1][1], b, x0, y0); break;
            default:fold_tg_body<3,8,8>(sb, g_att_tg[0], g_memB_tg[0], g_feats[1][0], b, x0, y0); break;
        }
    }
}

// ---------------- fusion ----------------
__global__ void pool_kernel() {
    int bi = blockIdx.x;                // 0..63
    int branch = bi >> 5;               // Bq*Cc = 32
    int r = bi & 31;
    const float* f0 = g_feats[branch][0] + (size_t)r*HWp;
    const float* f1 = g_feats[branch][1] + (size_t)r*HWp;
    const float* f2 = g_feats[branch][2] + (size_t)r*HWp;
    float sv = 0.f;
    for (int i = threadIdx.x; i < HWp; i += blockDim.x)
        sv += f0[i] + f1[i] + f2[i];
    __shared__ float red[256];
    red[threadIdx.x] = sv;
    __syncthreads();
    for (int off = 128; off > 0; off >>= 1) {
        if (threadIdx.x < off) red[threadIdx.x] += red[threadIdx.x + off];
        __syncthreads();
    }
    if (threadIdx.x == 0) g_pooled[branch][r] = red[0] / (float)HWp;
}

__global__ void fuse_wt_kernel(const float* __restrict__ bw1, const float* __restrict__ bb1,
                               const float* __restrict__ bw2, const float* __restrict__ bb2,
                               const float* __restrict__ tw1, const float* __restrict__ tb1,
                               const float* __restrict__ tw2, const float* __restrict__ tb2) {
    int t = threadIdx.x;
    if (t >= 2*Bq*Cc) return;
    int branch = t / (Bq*Cc);
    int r = t % (Bq*Cc);
    int b = r / Cc, c = r % Cc;
    const float* w1 = branch ? tw1 : bw1;
    const float* b1 = branch ? tb1 : bb1;
    const float* w2 = branch ? tw2 : bw2;
    const float* b2 = branch ? tb2 : bb2;
    float hdn[4];
    for (int h = 0; h < 4; h++) {
        float sv = b1[h];
        for (int cc = 0; cc < Cc; cc++) sv += w1[h*Cc+cc] * g_pooled[branch][b*Cc+cc];
        hdn[h] = fmaxf(sv, 0.f);
    }
    float lg[3];
    for (int si = 0; si < 3; si++) {
        int row = si*Cc + c;
        float sv = b2[row];
        for (int h = 0; h < 4; h++) sv += w2[row*4+h]*hdn[h];
        lg[si] = sv;
    }
    float mx = fmaxf(lg[0], fmaxf(lg[1], lg[2]));
    float e0 = __expf(lg[0]-mx), e1 = __expf(lg[1]-mx), e2 = __expf(lg[2]-mx);
    float inv = 1.f/(e0+e1+e2);
    g_wt[branch][(b*3+0)*Cc+c] = e0*inv;
    g_wt[branch][(b*3+1)*Cc+c] = e1*inv;
    g_wt[branch][(b*3+2)*Cc+c] = e2*inv;
}

__global__ void combine_kernel(float* __restrict__ out) {
    const size_t N1 = (size_t)Bq*Cc*HWp;
    size_t idx = (size_t)blockIdx.x*blockDim.x + threadIdx.x;
    if (idx >= 2*N1) return;
    int branch = (int)(idx / N1);
    size_t r = idx % N1;
    int b = (int)(r / ((size_t)Cc*HWp));
    int c = (int)((r / HWp) % Cc);
    float w0 = g_wt[branch][(b*3+0)*Cc+c];
    float w1 = g_wt[branch][(b*3+1)*Cc+c];
    float w2 = g_wt[branch][(b*3+2)*Cc+c];
    out[idx] = g_feats[branch][0][r]*w0 + g_feats[branch][1][r]*w1 + g_feats[branch][2][r]*w2;
}

// ---------------- host launch ----------------
extern "C" void kernel_launch(void* const* d_in, const int* in_sizes, int n_in,
                              void* d_out, int out_size) {
    const float *bg = nullptr, *tg = nullptr;
    const float *bg_mem[3] = {}, *tg_mem[3] = {};
    const float *temp_bg[3] = {}, *temp_tg[3] = {};
    const float *f1w[2] = {}, *f1b[2] = {}, *f2w[2] = {}, *f2b[2] = {};
    int n_img = 0, n_t = 0, n_f1w = 0, n_f1b = 0, n_f2w = 0, n_f2b = 0;

    for (int i = 0; i < n_in; i++) {
        const float* p = (const float*)d_in[i];
        switch (in_sizes[i]) {
            case Bq*Cc*HWp: if (n_img++ == 0) bg = p; else tg = p; break;
            case 64*144: bg_mem[0] = p; break;
            case 64*400: bg_mem[1] = p; break;
            case 64*784: bg_mem[2] = p; break;
            case 8*144:  tg_mem[0] = p; break;
            case 8*400:  tg_mem[1] = p; break;
            case 8*784:  tg_mem[2] = p; break;
            case 1: {   // all temps are identical (10.0), ordering-immune
                int k = n_t++;
                if (k < 6) { if (k % 2 == 0) temp_bg[k/2] = p; else temp_tg[k/2] = p; }
                break; }
            case 64:  { if (n_f1w < 2) f1w[n_f1w] = p; n_f1w++; break; }
            case 4:   { if (n_f1b < 2) f1b[n_f1b] = p; n_f1b++; break; }
            case 192: { if (n_f2w < 2) f2w[n_f2w] = p; n_f2w++; break; }
            case 48:  { if (n_f2b < 2) f2b[n_f2b] = p; n_f2b++; break; }
            default: break;
        }
    }

    // 1) transpose all memories (one launch)
    transpose_all_kernel<<<dim3(16,6), 256>>>(bg_mem[0], bg_mem[1], bg_mem[2],
                                              tg_mem[0], tg_mem[1], tg_mem[2]);

    // 2) sim + softmax -> att maps (one fused launch, heavy first)
    logits_all_kernel<<<768, NT>>>(bg, tg,
                                   temp_bg[2], temp_bg[1], temp_bg[0],
                                   temp_tg[2], temp_tg[1], temp_tg[0]);

    // 3) readout + fold + divisor -> per-scale feats (one fused launch)
    fold_all_kernel<<<480, NT>>>();

    // 4) fusion
    pool_kernel<<<2*Bq*Cc, 256>>>();
    fuse_wt_kernel<<<1, 64>>>(f1w[0], f1b[0], f2w[0], f2b[0],
                              f1w[1], f1b[1], f2w[1], f2b[1]);
    const size_t Ntot = (size_t)2*Bq*Cc*HWp;
    combine_kernel<<<(unsigned)((Ntot + 255)/256), 256>>>((float*)d_out);
}